// round 3
// baseline (speedup 1.0000x reference)
#include <cuda_runtime.h>
#include <math.h>

#define TSTEPS  2048
#define FDIM    15
#define UD      256
#define NGROUPS 8
#define BG      8      // batch rows per group
#define NSLICE  16
#define NT      384
#define NCTA    (NGROUPS * NSLICE)
#define SP      260    // padded SMEM row stride (floats) to kill bank conflicts

// Double-buffered hidden states (tiny: live in L2)
__device__ float    g_h1[2 * NGROUPS * BG * UD];
__device__ float    g_h2[2 * NGROUPS * BG * UD];
__device__ unsigned g_bar[NGROUPS];

__global__ void init_kernel() {
    if (threadIdx.x < NGROUPS) g_bar[threadIdx.x] = 0u;
}

__device__ __forceinline__ float sigmoidf_(float x) {
    return 1.0f / (1.0f + expf(-x));
}

// Group barrier: monotonic counter in L2. Release = threadfence+atomicAdd,
// acquire = volatile spin + threadfence, broadcast via bar.sync.
__device__ __forceinline__ void group_barrier(unsigned* cnt, unsigned target) {
    __syncthreads();
    if (threadIdx.x == 0) {
        __threadfence();
        atomicAdd(cnt, 1u);
        while (*((volatile unsigned*)cnt) < target) { }
        __threadfence();
    }
    __syncthreads();
}

__global__ void __launch_bounds__(NT, 1)
gru_kernel(const float* __restrict__ inp, const float* __restrict__ W1,
           const float* __restrict__ U1g, const float* __restrict__ b1,
           const float* __restrict__ W2g, const float* __restrict__ U2g,
           const float* __restrict__ b2, float* __restrict__ out)
{
    extern __shared__ float smem[];
    float* sBA   = smem;                 // [96][SP]  cols 0..47 = U1 slice, 48..95 = W2 slice (transposed)
    float* sU2t  = sBA  + 96 * SP;       // [48][SP]
    float* sh1   = sU2t + 48 * SP;       // [8][SP]   h1[i-1]
    float* sh2   = sh1  +  8 * SP;       // [8][SP]   h2[i-2]
    float* sW1t  = sh2  +  8 * SP;       // [48][16]
    float* sx    = sW1t + 48 * 16;       // [8][16]
    float* sb    = sx   +  8 * 16;       // [4*48] : b1_in | b1_rec | b2_in | b2_rec (slice cols)
    float* sacc1 = sb   +  4 * 48;       // [8][96]
    float* sacc2 = sacc1 + 8 * 96;       // [8][48]

    const int tid   = threadIdx.x;
    const int grp   = blockIdx.x >> 4;
    const int sl    = blockIdx.x & 15;
    const int brow0 = grp * BG;

    // ---- one-time: load weight slices (transposed) into SMEM ----
    for (int idx = tid; idx < 48 * 256; idx += NT) {
        int k = idx / 48, c = idx - k * 48;
        int col = ((c >> 4) << 8) + (sl << 4) + (c & 15);   // gate*256 + slice*16 + u
        sBA [c * SP + k]        = U1g[k * 768 + col];
        sBA [(48 + c) * SP + k] = W2g[k * 768 + col];
        sU2t[c * SP + k]        = U2g[k * 768 + col];
    }
    for (int idx = tid; idx < 48 * 15; idx += NT) {
        int f = idx / 48, c = idx - f * 48;
        int col = ((c >> 4) << 8) + (sl << 4) + (c & 15);
        sW1t[c * 16 + f] = W1[f * 768 + col];
    }
    for (int c = tid; c < 48; c += NT) {
        int col = ((c >> 4) << 8) + (sl << 4) + (c & 15);
        sb[c]        = b1[col];
        sb[48 + c]   = b1[768 + col];
        sb[96 + c]   = b2[col];
        sb[144 + c]  = b2[768 + col];
    }
    // zero our slice of both buffers of both states
    if (tid < 128) {
        int b = tid & 7, u = tid >> 3;
        int scol = (sl << 4) + u;
        for (int buf = 0; buf < 2; buf++) {
            g_h1[(buf * NGROUPS + grp) * BG * UD + b * UD + scol] = 0.f;
            g_h2[(buf * NGROUPS + grp) * BG * UD + b * UD + scol] = 0.f;
        }
    }

    unsigned epoch = 1;
    group_barrier(&g_bar[grp], 16u * epoch);
    epoch++;

    for (int i = 0; i <= TSTEPS; ++i) {
        // ---- phase 1: load shared state (L2-coherent loads) + input row ----
        const float* gh1 = g_h1 + (((i + 1) & 1) * NGROUPS + grp) * BG * UD;   // h1[i-1]
        const float* gh2 = g_h2 + (((i) & 1)     * NGROUPS + grp) * BG * UD;   // h2[i-2]
        for (int idx = tid; idx < 512; idx += NT) {
            int b = idx >> 6, k4 = idx & 63;
            float4 v1 = __ldcg(((const float4*)(gh1 + b * UD)) + k4);
            float4 v2 = __ldcg(((const float4*)(gh2 + b * UD)) + k4);
            *(float4*)(sh1 + b * SP + (k4 << 2)) = v1;
            *(float4*)(sh2 + b * SP + (k4 << 2)) = v2;
        }
        if (i < TSTEPS && tid < 120) {
            int b = tid / 15, f = tid - b * 15;
            sx[b * 16 + f] = inp[(brow0 + b) * (TSTEPS * FDIM) + i * FDIM + f];
        }
        __syncthreads();

        // ---- phase 2a: fused GEMM  [rec1 | xp2] = h1_prev @ [U1 | W2]  (8x96x256) ----
        {
            int b = tid & 7, cp = tid >> 3;           // cp 0..47 -> cols 2cp, 2cp+1
            const float* hr = sh1 + b * SP;
            const float* u0 = sBA + (2 * cp) * SP;
            const float* u1 = u0 + SP;
            float4 a0 = make_float4(0.f, 0.f, 0.f, 0.f);
            float4 a1 = make_float4(0.f, 0.f, 0.f, 0.f);
            #pragma unroll 8
            for (int k = 0; k < 256; k += 4) {
                float4 h4 = *(const float4*)(hr + k);
                float4 x0 = *(const float4*)(u0 + k);
                float4 x1 = *(const float4*)(u1 + k);
                a0.x += h4.x * x0.x;  a0.y += h4.y * x0.y;
                a0.z += h4.z * x0.z;  a0.w += h4.w * x0.w;
                a1.x += h4.x * x1.x;  a1.y += h4.y * x1.y;
                a1.z += h4.z * x1.z;  a1.w += h4.w * x1.w;
            }
            sacc1[b * 96 + 2 * cp]     = (a0.x + a0.y) + (a0.z + a0.w);
            sacc1[b * 96 + 2 * cp + 1] = (a1.x + a1.y) + (a1.z + a1.w);
        }
        // ---- phase 2b: rec2 = h2_prev @ U2  (8x48x256) ----
        {
            int b = tid & 7, c = tid >> 3;            // c 0..47
            const float* hr = sh2 + b * SP;
            const float* u0 = sU2t + c * SP;
            float4 a0 = make_float4(0.f, 0.f, 0.f, 0.f);
            #pragma unroll 8
            for (int k = 0; k < 256; k += 4) {
                float4 h4 = *(const float4*)(hr + k);
                float4 x0 = *(const float4*)(u0 + k);
                a0.x += h4.x * x0.x;  a0.y += h4.y * x0.y;
                a0.z += h4.z * x0.z;  a0.w += h4.w * x0.w;
            }
            sacc2[b * 48 + c] = (a0.x + a0.y) + (a0.z + a0.w);
        }
        __syncthreads();

        // ---- phase 3: gates + state update (128 threads: one (b,u) each) ----
        if (tid < 128) {
            int b = tid & 7, u = tid >> 3;
            int scol = (sl << 4) + u;
            int gb = brow0 + b;

            if (i < TSTEPS) {   // layer 1: h1[i]
                float xp[3], rec[3];
                #pragma unroll
                for (int gci = 0; gci < 3; gci++) {
                    int c = gci * 16 + u;
                    float acc = sb[c];                          // b1_in
                    const float* wr = sW1t + c * 16;
                    const float* xr = sx + b * 16;
                    #pragma unroll
                    for (int f = 0; f < 15; f++) acc += xr[f] * wr[f];
                    xp[gci]  = acc;
                    rec[gci] = sacc1[b * 96 + c] + sb[48 + c];  // + b1_rec
                }
                float z  = sigmoidf_(xp[0] + rec[0]);
                float r  = sigmoidf_(xp[1] + rec[1]);
                float hh = fmaxf(0.f, xp[2] + r * rec[2]);
                float hp = sh1[b * SP + scol];
                float hn = z * hp + (1.f - z) * hh;
                g_h1[((i & 1) * NGROUPS + grp) * BG * UD + b * UD + scol] = hn;
                if (i == TSTEPS - 1) out[64 * 256 + gb * 256 + scol] = hn;   // state1
            }
            if (i >= 1) {       // layer 2: h2[i-1]
                float xpz = sacc1[b * 96 + 48 + u]       + sb[96 + u];
                float xpr = sacc1[b * 96 + 48 + 16 + u]  + sb[96 + 16 + u];
                float xph = sacc1[b * 96 + 48 + 32 + u]  + sb[96 + 32 + u];
                float rcz = sacc2[b * 48 + u]            + sb[144 + u];
                float rcr = sacc2[b * 48 + 16 + u]       + sb[144 + 16 + u];
                float rch = sacc2[b * 48 + 32 + u]       + sb[144 + 32 + u];
                float z  = sigmoidf_(xpz + rcz);
                float r  = sigmoidf_(xpr + rcr);
                float hh = fmaxf(0.f, xph + r * rch);
                float hp = sh2[b * SP + scol];
                float hn = z * hp + (1.f - z) * hh;
                g_h2[(((i - 1) & 1) * NGROUPS + grp) * BG * UD + b * UD + scol] = hn;
                if (i == TSTEPS) {
                    out[gb * 256 + scol]                 = hn;   // x = seq2[:, -1, :]
                    out[2 * 64 * 256 + gb * 256 + scol]  = hn;   // state2
                }
            }
        }

        if (i < TSTEPS) group_barrier(&g_bar[grp], 16u * epoch);
        epoch++;
    }
}

extern "C" void kernel_launch(void* const* d_in, const int* in_sizes, int n_in,
                              void* d_out, int out_size) {
    const float* inp = (const float*)d_in[0];
    const float* W1  = (const float*)d_in[1];
    const float* U1  = (const float*)d_in[2];
    const float* b1  = (const float*)d_in[3];
    const float* W2  = (const float*)d_in[4];
    const float* U2  = (const float*)d_in[5];
    const float* b2  = (const float*)d_in[6];
    float* out = (float*)d_out;

    size_t smem_bytes = (size_t)(96 * SP + 48 * SP + 8 * SP + 8 * SP +
                                 48 * 16 + 8 * 16 + 4 * 48 + 8 * 96 + 8 * 48) * sizeof(float);
    cudaFuncSetAttribute(gru_kernel, cudaFuncAttributeMaxDynamicSharedMemorySize,
                         (int)smem_bytes);
    init_kernel<<<1, 32>>>();
    gru_kernel<<<NCTA, NT, smem_bytes>>>(inp, W1, U1, b1, W2, U2, b2, out);
}

// round 4
// speedup vs baseline: 2.6628x; 2.6628x over previous
#include <cuda_runtime.h>
#include <math.h>

#define TSTEPS  2048
#define FDIM    15
#define UD      256
#define NGROUPS 8
#define BG      8      // batch rows per group
#define NSLICE  16
#define NT      384
#define NCTA    (NGROUPS * NSLICE)
#define SP      260    // padded row stride for h state (floats)
#define WS      260    // padded row stride for weights (floats)
#define RS      1160   // padded stride for reduction buffer (floats)

// Double-buffered hidden states (tiny: live in L2)
__device__ float    g_h1[2 * NGROUPS * BG * UD];
__device__ float    g_h2[2 * NGROUPS * BG * UD];
__device__ unsigned g_bar[NGROUPS];

__global__ void init_kernel() {
    if (threadIdx.x < NGROUPS) g_bar[threadIdx.x] = 0u;
}

__device__ __forceinline__ float sigmoidf_(float x) {
    return __fdividef(1.0f, 1.0f + __expf(-x));
}

// Group barrier: monotonic counter in L2.
__device__ __forceinline__ void group_barrier(unsigned* cnt, unsigned target) {
    __syncthreads();
    if (threadIdx.x == 0) {
        __threadfence();
        atomicAdd(cnt, 1u);
        while (*((volatile unsigned*)cnt) < target) { }
        __threadfence();
    }
    __syncthreads();
}

__global__ void __launch_bounds__(NT, 1)
gru_kernel(const float* __restrict__ inp, const float* __restrict__ W1,
           const float* __restrict__ U1g, const float* __restrict__ b1,
           const float* __restrict__ W2g, const float* __restrict__ U2g,
           const float* __restrict__ b2, float* __restrict__ out)
{
    extern __shared__ float smem[];
    // layout (floats):
    float* sW    = smem;                  // [144][WS]  rows 0..47 U1, 48..95 W2, 96..143 U2 (transposed)
    float* sh1   = sW    + 144 * WS;      // [8][SP]   h1[i-1]
    float* sh2   = sh1   +   8 * SP;      // [8][SP]   h2[i-2]
    float* sW1t  = sh2   +   8 * SP;      // [48][16]
    float* sx    = sW1t  +  48 * 16;      // [8][16]
    float* sb    = sx    +   8 * 16;      // [4*48] : b1_in | b1_rec | b2_in | b2_rec
    float* sacc1 = sb    +   4 * 48;      // [8][96]
    float* sacc2 = sacc1 +   8 * 96;      // [8][48]
    float* red   = sacc2 +   8 * 48;      // [8][RS]  k-split partials

    const int tid   = threadIdx.x;
    const int grp   = blockIdx.x >> 4;
    const int sl    = blockIdx.x & 15;
    const int brow0 = grp * BG;

    // ---- one-time: load weight slices (transposed) into SMEM ----
    for (int idx = tid; idx < 48 * 256; idx += NT) {
        int k = idx / 48, c = idx - k * 48;
        int col = ((c >> 4) << 8) + (sl << 4) + (c & 15);   // gate*256 + slice*16 + u
        sW[c * WS + k]          = U1g[k * 768 + col];
        sW[(48 + c) * WS + k]   = W2g[k * 768 + col];
        sW[(96 + c) * WS + k]   = U2g[k * 768 + col];
    }
    for (int idx = tid; idx < 48 * 15; idx += NT) {
        int f = idx / 48, c = idx - f * 48;
        int col = ((c >> 4) << 8) + (sl << 4) + (c & 15);
        sW1t[c * 16 + f] = W1[f * 768 + col];
    }
    for (int c = tid; c < 48; c += NT) {
        int col = ((c >> 4) << 8) + (sl << 4) + (c & 15);
        sb[c]        = b1[col];
        sb[48 + c]   = b1[768 + col];
        sb[96 + c]   = b2[col];
        sb[144 + c]  = b2[768 + col];
    }
    if (tid < 128) {
        int b = tid & 7, u = tid >> 3;
        int scol = (sl << 4) + u;
        for (int buf = 0; buf < 2; buf++) {
            g_h1[(buf * NGROUPS + grp) * BG * UD + b * UD + scol] = 0.f;
            g_h2[(buf * NGROUPS + grp) * BG * UD + b * UD + scol] = 0.f;
        }
    }

    // thread tile decomposition for the fused GEMM
    const int kc  = tid / 48;          // 0..7  (k chunk of 32)
    const int r48 = tid - kc * 48;
    const int cg  = r48 >> 1;          // 0..23 (6 columns each)
    const int rh  = r48 & 1;           // 0..1  (4 rows each)
    const float* hsel  = (cg < 16 ? sh1 : sh2) + rh * 4 * SP + kc * 32;
    const float* wbase = sW + (cg * 6) * WS + kc * 32;

    unsigned epoch = 1;
    group_barrier(&g_bar[grp], 16u * epoch);
    epoch++;

    for (int i = 0; i <= TSTEPS; ++i) {
        // ---- phase 1: load shared state (L2-coherent) + input row ----
        const float* gh1 = g_h1 + (((i + 1) & 1) * NGROUPS + grp) * BG * UD;   // h1[i-1]
        const float* gh2 = g_h2 + (((i) & 1)     * NGROUPS + grp) * BG * UD;   // h2[i-2]
        for (int idx = tid; idx < 512; idx += NT) {
            int b = idx >> 6, k4 = idx & 63;
            float4 v1 = __ldcg(((const float4*)(gh1 + b * UD)) + k4);
            float4 v2 = __ldcg(((const float4*)(gh2 + b * UD)) + k4);
            *(float4*)(sh1 + b * SP + (k4 << 2)) = v1;
            *(float4*)(sh2 + b * SP + (k4 << 2)) = v2;
        }
        if (i < TSTEPS && tid < 120) {
            int b = tid / 15, f = tid - b * 15;
            sx[b * 16 + f] = inp[(brow0 + b) * (TSTEPS * FDIM) + i * FDIM + f];
        }
        __syncthreads();

        // ---- phase 2: fused register-tiled GEMM ----
        // outputs: [8 rows][144 cols]; cols 0..95 = h1 @ [U1|W2], 96..143 = h2 @ U2
        {
            float acc[4][6];
            #pragma unroll
            for (int j = 0; j < 4; j++)
                #pragma unroll
                for (int jj = 0; jj < 6; jj++) acc[j][jj] = 0.f;

            #pragma unroll
            for (int s = 0; s < 8; s++) {
                float4 h4[4];
                #pragma unroll
                for (int j = 0; j < 4; j++)
                    h4[j] = *(const float4*)(hsel + j * SP + s * 4);
                #pragma unroll
                for (int jj = 0; jj < 6; jj++) {
                    float4 w4 = *(const float4*)(wbase + jj * WS + s * 4);
                    #pragma unroll
                    for (int j = 0; j < 4; j++) {
                        acc[j][jj] += h4[j].x * w4.x;
                        acc[j][jj] += h4[j].y * w4.y;
                        acc[j][jj] += h4[j].z * w4.z;
                        acc[j][jj] += h4[j].w * w4.w;
                    }
                }
            }
            // write k-split partials: red[kc][row*144 + col]
            #pragma unroll
            for (int j = 0; j < 4; j++) {
                int row = rh * 4 + j;
                #pragma unroll
                for (int jj = 0; jj < 6; jj += 2) {
                    int o = row * 144 + cg * 6 + jj;
                    *(float2*)&red[kc * RS + o] = make_float2(acc[j][jj], acc[j][jj + 1]);
                }
            }
        }
        __syncthreads();

        // ---- phase 2c: reduce over kc (3 outputs per thread) ----
        #pragma unroll
        for (int t = 0; t < 3; t++) {
            int o = tid * 3 + t;
            float s = red[o];
            #pragma unroll
            for (int k2 = 1; k2 < 8; k2++) s += red[k2 * RS + o];
            int row = o / 144, col = o - row * 144;
            if (col < 96) sacc1[row * 96 + col] = s;
            else          sacc2[row * 48 + (col - 96)] = s;
        }
        __syncthreads();

        // ---- phase 3: gates + state update (128 threads: one (b,u) each) ----
        if (tid < 128) {
            int b = tid & 7, u = tid >> 3;
            int scol = (sl << 4) + u;
            int gb = brow0 + b;

            if (i < TSTEPS) {   // layer 1: h1[i]
                float xp[3], rec[3];
                #pragma unroll
                for (int gci = 0; gci < 3; gci++) {
                    int c = gci * 16 + u;
                    float acc = sb[c];                          // b1_in
                    const float* wr = sW1t + c * 16;
                    const float* xr = sx + b * 16;
                    #pragma unroll
                    for (int f = 0; f < 15; f++) acc += xr[f] * wr[f];
                    xp[gci]  = acc;
                    rec[gci] = sacc1[b * 96 + c] + sb[48 + c];  // + b1_rec
                }
                float z  = sigmoidf_(xp[0] + rec[0]);
                float r  = sigmoidf_(xp[1] + rec[1]);
                float hh = fmaxf(0.f, xp[2] + r * rec[2]);
                float hp = sh1[b * SP + scol];
                float hn = z * hp + (1.f - z) * hh;
                g_h1[((i & 1) * NGROUPS + grp) * BG * UD + b * UD + scol] = hn;
                if (i == TSTEPS - 1) out[64 * 256 + gb * 256 + scol] = hn;   // state1
            }
            if (i >= 1) {       // layer 2: h2[i-1]
                float xpz = sacc1[b * 96 + 48 + u]       + sb[96 + u];
                float xpr = sacc1[b * 96 + 48 + 16 + u]  + sb[96 + 16 + u];
                float xph = sacc1[b * 96 + 48 + 32 + u]  + sb[96 + 32 + u];
                float rcz = sacc2[b * 48 + u]            + sb[144 + u];
                float rcr = sacc2[b * 48 + 16 + u]       + sb[144 + 16 + u];
                float rch = sacc2[b * 48 + 32 + u]       + sb[144 + 32 + u];
                float z  = sigmoidf_(xpz + rcz);
                float r  = sigmoidf_(xpr + rcr);
                float hh = fmaxf(0.f, xph + r * rch);
                float hp = sh2[b * SP + scol];
                float hn = z * hp + (1.f - z) * hh;
                g_h2[(((i - 1) & 1) * NGROUPS + grp) * BG * UD + b * UD + scol] = hn;
                if (i == TSTEPS) {
                    out[gb * 256 + scol]                 = hn;   // x = seq2[:, -1, :]
                    out[2 * 64 * 256 + gb * 256 + scol]  = hn;   // state2
                }
            }
        }

        if (i < TSTEPS) group_barrier(&g_bar[grp], 16u * epoch);
        epoch++;
    }
}

extern "C" void kernel_launch(void* const* d_in, const int* in_sizes, int n_in,
                              void* d_out, int out_size) {
    const float* inp = (const float*)d_in[0];
    const float* W1  = (const float*)d_in[1];
    const float* U1  = (const float*)d_in[2];
    const float* b1  = (const float*)d_in[3];
    const float* W2  = (const float*)d_in[4];
    const float* U2  = (const float*)d_in[5];
    const float* b2  = (const float*)d_in[6];
    float* out = (float*)d_out;

    size_t smem_bytes = (size_t)(144 * WS + 8 * SP + 8 * SP +
                                 48 * 16 + 8 * 16 + 4 * 48 +
                                 8 * 96 + 8 * 48 + 8 * RS) * sizeof(float);
    cudaFuncSetAttribute(gru_kernel, cudaFuncAttributeMaxDynamicSharedMemorySize,
                         (int)smem_bytes);
    init_kernel<<<1, 32>>>();
    gru_kernel<<<NCTA, NT, smem_bytes>>>(inp, W1, U1, b1, W2, U2, b2, out);
}